// round 1
// baseline (speedup 1.0000x reference)
#include <cuda_runtime.h>
#include <cstdint>

typedef unsigned long long ull;

// Packed weight pairs: g_wpk[(k*16 + i)*32 + o] = (lo=W[o,i,0,k], hi=W[o,i,1,k])
__device__ __align__(16) ull g_wpk[4608];

__global__ void prep_weights_kernel(const float* __restrict__ w) {
    int idx = blockIdx.x * blockDim.x + threadIdx.x;
    if (idx >= 4608) return;
    int k = idx >> 9;           // 0..8
    int i = (idx >> 5) & 15;    // 0..15
    int o = idx & 31;           // 0..31
    // weight layout: w[o][i][d][kh][kw] -> (o*16+i)*27 + d*9 + k
    float w0 = w[(o * 16 + i) * 27 + 0 + k];
    float w1 = w[(o * 16 + i) * 27 + 9 + k];
    g_wpk[idx] = ((ull)__float_as_uint(w1) << 32) | (ull)__float_as_uint(w0);
}

#define FMA2(acc, a, b) asm("fma.rn.f32x2 %0, %1, %2, %0;" : "+l"(acc) : "l"(a), "l"(b))

__global__ __launch_bounds__(256, 2)
void depconv_main(const float* __restrict__ feat,
                  const int* __restrict__ depth,
                  float* __restrict__ out) {
    __shared__ __align__(16) ull wsm[4608];   // 36864 B
    __shared__ float xs[8][10][34];           // 10880 B (8-ch chunk + halo)
    __shared__ int   dt[10][34];              // 1360 B

    const int b   = blockIdx.z;
    const int h0  = blockIdx.y * 8;
    const int w0  = blockIdx.x * 32;
    const int tid = threadIdx.x;

    // Stage packed weights (coalesced, L2-resident)
    for (int t = tid; t < 4608; t += 256) wsm[t] = g_wpk[t];

    // Depth tile with halo (OOB value irrelevant: feature there is 0)
    for (int t = tid; t < 340; t += 256) {
        int rr = t / 34, cc = t % 34;
        int h = h0 - 1 + rr, w = w0 - 1 + cc;
        int v = 0;
        if ((unsigned)h < 512u && (unsigned)w < 512u) v = depth[(b * 512 + h) * 512 + w];
        dt[rr][cc] = v;
    }
    __syncthreads();

    const int g    = tid & 63;     // 64 pixel-group threads
    const int och  = tid >> 6;     // o-chunk 0..3 (warps never straddle)
    const int c    = g & 31;       // column within tile
    const int rblk = (g >> 5) * 4; // row block 0 or 4

    // Per-pixel 9-tap gating codes: bit k of codeA => slice0 (diff==-1),
    // bit k of codeB => slice1 (diff==0). Otherwise tap contributes zero.
    int codeA[4], codeB[4];
    #pragma unroll
    for (int p = 0; p < 4; p++) {
        int dc = dt[rblk + p + 1][c + 1];
        int A = 0, B = 0;
        #pragma unroll
        for (int k = 0; k < 9; k++) {
            int dn = dt[rblk + p + (k / 3)][c + (k % 3)];
            int diff = dn - dc;
            A |= (diff == -1) ? (1 << k) : 0;
            B |= (diff ==  0) ? (1 << k) : 0;
        }
        codeA[p] = A; codeB[p] = B;
    }

    // 4 pixels x 8 output channels, packed (slice0, slice1) accumulators
    ull acc[4][8];
    #pragma unroll
    for (int p = 0; p < 4; p++)
        #pragma unroll
        for (int o = 0; o < 8; o++) acc[p][o] = 0ull;

    #pragma unroll 1
    for (int icb = 0; icb < 2; icb++) {
        __syncthreads();  // xs reuse guard (no-op cost on first iter)
        // Stage 8 feature channels with halo
        for (int t = tid; t < 8 * 340; t += 256) {
            int i  = t / 340;
            int rr = (t / 34) % 10, cc = t % 34;
            int h = h0 - 1 + rr, w = w0 - 1 + cc;
            float v = 0.f;
            if ((unsigned)h < 512u && (unsigned)w < 512u)
                v = feat[((b * 16 + icb * 8 + i) * 512 + h) * 512 + w];
            xs[i][rr][cc] = v;
        }
        __syncthreads();

        #pragma unroll
        for (int k = 0; k < 9; k++) {
            const int kh = k / 3, kw = k % 3;
            int m0[4], m1[4];
            #pragma unroll
            for (int p = 0; p < 4; p++) {
                m0[p] = -((codeA[p] >> k) & 1);
                m1[p] = -((codeB[p] >> k) & 1);
            }
            const ull* wrow = &wsm[(k * 16 + icb * 8) * 32 + och * 8];
            #pragma unroll 2
            for (int i = 0; i < 8; i++) {
                // 8 packed weight pairs for this (k, i, o-chunk): broadcast LDS.128
                const ulonglong2* wp = (const ulonglong2*)(wrow + i * 32);
                ulonglong2 wv0 = wp[0], wv1 = wp[1], wv2 = wp[2], wv3 = wp[3];
                #pragma unroll
                for (int p = 0; p < 4; p++) {
                    int xi = __float_as_int(xs[i][rblk + p + kh][c + kw]);
                    ull xp;  // (x gated to slice0, x gated to slice1)
                    asm("mov.b64 %0, {%1, %2};"
                        : "=l"(xp) : "r"(xi & m0[p]), "r"(xi & m1[p]));
                    FMA2(acc[p][0], xp, wv0.x);
                    FMA2(acc[p][1], xp, wv0.y);
                    FMA2(acc[p][2], xp, wv1.x);
                    FMA2(acc[p][3], xp, wv1.y);
                    FMA2(acc[p][4], xp, wv2.x);
                    FMA2(acc[p][5], xp, wv2.y);
                    FMA2(acc[p][6], xp, wv3.x);
                    FMA2(acc[p][7], xp, wv3.y);
                }
            }
        }
    }

    // Epilogue: fold the two slice lanes and store (coalesced over c)
    #pragma unroll
    for (int p = 0; p < 4; p++) {
        int h = h0 + rblk + p;
        #pragma unroll
        for (int o = 0; o < 8; o++) {
            float lo, hi;
            asm("mov.b64 {%0, %1}, %2;" : "=f"(lo), "=f"(hi) : "l"(acc[p][o]));
            out[((b * 32 + och * 8 + o) * 512 + h) * 512 + w0 + c] = lo + hi;
        }
    }
}

extern "C" void kernel_launch(void* const* d_in, const int* in_sizes, int n_in,
                              void* d_out, int out_size) {
    const float* feat  = (const float*)d_in[0];   // (4,16,512,512) f32
    const int*   depth = (const int*)d_in[1];     // (4,512,512) i32
    const float* w     = (const float*)d_in[2];   // (32,16,3,3,3) f32
    float* out = (float*)d_out;                   // (4,32,512,512) f32

    prep_weights_kernel<<<18, 256>>>(w);
    dim3 grid(16, 64, 4);                         // (w-tiles, h-tiles, batch)
    depconv_main<<<grid, 256>>>(feat, depth, out);
}

// round 3
// speedup vs baseline: 6.3292x; 6.3292x over previous
#include <cuda_runtime.h>
#include <cuda_fp16.h>
#include <cstdint>

static constexpr int N_TILES = 8192;   // 16 (w) x 128 (h) x 4 (batch)

#define MMA16816(c, a0, a1, a2, a3, b0, b1) \
    asm volatile( \
        "mma.sync.aligned.m16n8k16.row.col.f32.f16.f16.f32 " \
        "{%0,%1,%2,%3}, {%4,%5,%6,%7}, {%8,%9}, {%0,%1,%2,%3};" \
        : "+f"((c)[0]), "+f"((c)[1]), "+f"((c)[2]), "+f"((c)[3]) \
        : "r"(a0), "r"(a1), "r"(a2), "r"(a3), "r"(b0), "r"(b1))

__global__ __launch_bounds__(128, 4)
void depconv_hmma(const float* __restrict__ feat,
                  const int* __restrict__ depth,
                  const float* __restrict__ wgt,
                  float* __restrict__ out) {
    // ftile[pix][ch]: pix = r*34+cc (6x34 halo tile), 16 fp16 channels (32B/pixel)
    __shared__ __align__(16) unsigned short ftile[204 * 16];     // 6528 B
    // Bsm[ks][n][ch]: ks = t*2+s (18), n = oc (32), ch = ic (16)
    __shared__ __align__(16) unsigned short Bsm[18 * 32 * 16];   // 18432 B
    __shared__ int dt[204];                                      // 816 B

    const int tid  = threadIdx.x;
    const int wid  = tid >> 5;        // warp = tile row 0..3
    const int lane = tid & 31;
    const int g    = lane >> 2;       // fragment group 0..7
    const int t4   = lane & 3;

    // ---- build B once per CTA (fp16, channel order = natural ic) ----
    for (int idx = tid; idx < 9216; idx += 128) {
        int ks = idx >> 9, rem = idx & 511;
        int n = rem >> 4, i = rem & 15;
        int t = ks >> 1, s = ks & 1;
        float v = wgt[(n * 16 + i) * 27 + s * 9 + t];
        Bsm[idx] = __half_as_ushort(__float2half_rn(v));
    }

    const char* fb = (const char*)ftile;
    const char* Bb = (const char*)Bsm;

    // thread-constant A base addresses for its 4 pixels (cols g, g+8, g+16, g+24)
    uint32_t aBase[4];
    #pragma unroll
    for (int p = 0; p < 4; p++)
        aBase[p] = (uint32_t)(((wid * 34) + g + p * 8) * 32 + t4 * 8);
    const uint32_t bBase = (uint32_t)(g * 32 + t4 * 8);

    const int ic2 = lane & 7;     // channel-pair lane for staging
    const int pf  = lane >> 3;    // pixel offset 0..3 for staging

    for (int tile = blockIdx.x; tile < N_TILES; tile += gridDim.x) {
        const int twi = tile & 15, thi = (tile >> 4) & 127, b = tile >> 11;
        const int h0 = thi * 4, w0 = twi * 32;

        // ---- stage depth halo (6 x 34) ----
        for (int idx = tid; idx < 204; idx += 128) {
            int r = idx / 34, cc = idx - r * 34;
            int h = h0 - 1 + r, w = w0 - 1 + cc;
            int v = 0;
            if ((unsigned)h < 512u && (unsigned)w < 512u)
                v = depth[(b * 512 + h) * 512 + w];
            dt[idx] = v;
        }
        // ---- stage features as fp16 pairs; bank-conflict-free STS.32 ----
        {
            const float* fp0 = feat + ((size_t)b * 16 + 2 * ic2) * 262144;
            for (int base = wid * 4; base < 204; base += 16) {
                int pix = base + pf;
                int r = pix / 34, cc = pix - r * 34;
                int h = h0 - 1 + r, w = w0 - 1 + cc;
                float v0 = 0.f, v1 = 0.f;
                if ((unsigned)h < 512u && (unsigned)w < 512u) {
                    v0 = fp0[h * 512 + w];
                    v1 = fp0[262144 + h * 512 + w];
                }
                __half2 hv = __floats2half2_rn(v0, v1);
                *(uint32_t*)((char*)ftile + pix * 32 + ic2 * 4) =
                    *reinterpret_cast<uint32_t*>(&hv);
            }
        }
        __syncthreads();

        // ---- per-pixel gating codes: bits[t] slice-1(-1), bits[16+t] slice0 ----
        int code[4];
        #pragma unroll
        for (int p = 0; p < 4; p++) {
            int pc = g + p * 8;
            int dc = dt[(wid + 1) * 34 + pc + 1];
            int A = 0, Bc = 0;
            #pragma unroll
            for (int t = 0; t < 9; t++) {
                int dn = dt[(wid + t / 3) * 34 + pc + t % 3];
                int diff = dn - dc;
                A  |= (diff == -1) ? (1 << t) : 0;
                Bc |= (diff == 0) ? (1 << t) : 0;
            }
            code[p] = A | (Bc << 16);
        }

        float acc[2][4][4];
        #pragma unroll
        for (int mt = 0; mt < 2; mt++)
            #pragma unroll
            for (int nt = 0; nt < 4; nt++)
                #pragma unroll
                for (int j = 0; j < 4; j++) acc[mt][nt][j] = 0.f;

        // ---- K loop: 9 taps x 2 slices, fully unrolled, base+imm LDS ----
        #pragma unroll
        for (int t = 0; t < 9; t++) {
            const int dOff = ((t / 3) * 34 + (t % 3)) * 32;
            uint32_t x[4][2];
            #pragma unroll
            for (int p = 0; p < 4; p++) {
                uint2 v = *(const uint2*)(fb + aBase[p] + dOff);
                x[p][0] = v.x; x[p][1] = v.y;
            }
            #pragma unroll
            for (int s = 0; s < 2; s++) {
                const int ks = t * 2 + s;
                uint32_t m[4];
                #pragma unroll
                for (int p = 0; p < 4; p++)
                    m[p] = (uint32_t)(-((code[p] >> (t + 16 * s)) & 1));
                uint2 bv[4];
                #pragma unroll
                for (int nt = 0; nt < 4; nt++)
                    bv[nt] = *(const uint2*)(Bb + ks * 1024 + nt * 256 + bBase);
                #pragma unroll
                for (int mt = 0; mt < 2; mt++) {
                    uint32_t a0 = x[2 * mt][0] & m[2 * mt];
                    uint32_t a1 = x[2 * mt + 1][0] & m[2 * mt + 1];
                    uint32_t a2 = x[2 * mt][1] & m[2 * mt];
                    uint32_t a3 = x[2 * mt + 1][1] & m[2 * mt + 1];
                    #pragma unroll
                    for (int nt = 0; nt < 4; nt++)
                        MMA16816(acc[mt][nt], a0, a1, a2, a3, bv[nt].x, bv[nt].y);
                }
            }
        }

        // ---- epilogue: direct STG (32B-sector-aligned groups of 8 lanes) ----
        const int h = h0 + wid;
        #pragma unroll
        for (int mt = 0; mt < 2; mt++) {
            int wpx = w0 + mt * 16 + g;
            #pragma unroll
            for (int nt = 0; nt < 4; nt++) {
                int oc = nt * 8 + t4 * 2;
                float* op = out + (((size_t)b * 32 + oc) * 512 + h) * 512;
                op[wpx]              = acc[mt][nt][0];
                op[262144 + wpx]     = acc[mt][nt][1];
                op[wpx + 8]          = acc[mt][nt][2];
                op[262144 + wpx + 8] = acc[mt][nt][3];
            }
        }
        __syncthreads();   // ftile/dt free before next tile's staging
    }
}

extern "C" void kernel_launch(void* const* d_in, const int* in_sizes, int n_in,
                              void* d_out, int out_size) {
    const float* feat  = (const float*)d_in[0];   // (4,16,512,512) f32
    const int*   depth = (const int*)d_in[1];     // (4,512,512) i32
    const float* wgt   = (const float*)d_in[2];   // (32,16,3,3,3) f32
    float* out = (float*)d_out;                   // (4,32,512,512) f32

    int dev = 0, sms = 148;
    cudaGetDevice(&dev);
    cudaDeviceGetAttribute(&sms, cudaDevAttrMultiProcessorCount, dev);
    int grid = 4 * sms;
    if (grid > N_TILES) grid = N_TILES;
    depconv_hmma<<<grid, 128>>>(feat, depth, wgt, out);
}